// round 14
// baseline (speedup 1.0000x reference)
#include <cuda_runtime.h>
#include <cuda_bf16.h>

#define N_PRED 2048
#define T_RUNS 16
#define M_BOX  2048
#define EPS_F  1e-7f

#define GBY     16
#define GBX     32
#define BIN_ORG (-28.0f)
#define INV_Y   (1.0f/42.0f)    // 16*42 = 672 covers [-28, 644)
#define INV_X   (1.0f/21.0f)    // 32*21 = 672
#define WH_MAX  55.0f           // box w,h in [5,55)
#define CAP     1280            // smem slab capacity (5 rows avg ~640)
#define SPCAP   256             // smem pred-list capacity (half-row avg ~64)

// ---- device scratch (no allocations allowed) ----
// Per-pred arrival counter: bits[16+]=arrivals, bits[0:16]=found-sum.
// Zero-initialized at load; the 16th arrival writes out[p] and resets to 0,
// so every graph replay starts from the same state. Exact & order-independent.
__device__ int g_cnt[N_PRED];

__device__ __forceinline__ int biny(float v) {
    int b = (int)floorf((v - BIN_ORG) * INV_Y);
    return min(max(b, 0), GBY - 1);
}
__device__ __forceinline__ int binx(float v) {
    int b = (int)floorf((v - BIN_ORG) * INV_X);
    return min(max(b, 0), GBX - 1);
}

#define IOU_CHECK(BX, BY, BZ, BW, NA)                            \
    {   float ix1 = fmaxf(a.x, (BX));                            \
        float iy1 = fmaxf(a.y, (BY));                            \
        float ix2 = fminf(a.z, (BZ));                            \
        float iy2 = fminf(a.w, (BW));                            \
        float dx  = fmaxf(ix2 - ix1, 0.0f);                      \
        float dy  = iy2 - iy1;   /* dy<0 => inter<=0 < thr */    \
        best = fmaxf(best, fmaf(3.0f, dx * dy, (NA))); }

// ---------------------------------------------------------------------------
// ONE kernel. CTA = (half, yr, t), 128 threads. Builds its slab locally from
// raw inputs (local 5x32 counting sort, L2-hot shared reads), compacts its
// preds locally, runs the R13 champion scan, and emits via g_cnt arrivals.
// No prep kernel, no second launch, no grid sync, no out pre-zeroing.
// ---------------------------------------------------------------------------
__global__ __launch_bounds__(128)
void fused_kernel(const float* __restrict__ pred,
                  const float* __restrict__ dropout_preds,
                  float* __restrict__ out)
{
    __shared__ float4 sbox[CAP];
    __shared__ float  snarea[CAP];
    __shared__ int    scnt[256];      // counts -> exclusive prefix (query)
    __shared__ int    soff[256];      // running scatter offsets
    __shared__ float4 spred[SPCAP];
    __shared__ int    sperm[SPCAP];
    __shared__ int    wsum[4];
    __shared__ int    npred_s;

    const int tid  = threadIdx.x;
    const int lane = tid & 31, wid = tid >> 5;
    const int half = blockIdx.x;
    const int yr   = blockIdx.y;
    const int t    = blockIdx.z;

    const int r0 = max(yr - 2, 0), r1 = min(yr + 2, GBY - 1);
    const int nb = (r1 - r0 + 1) * GBX;           // <= 160 local bins

    scnt[tid] = 0; scnt[tid + 128] = 0;
    if (tid == 0) npred_s = 0;
    __syncthreads();

    const float* __restrict__ src = dropout_preds + (size_t)t * M_BOX * 6;

    // ---- pass 1: count boxes of run t falling in rows [r0, r1] ----
    #pragma unroll
    for (int k = 0; k < M_BOX / 128; ++k) {
        const int i = tid + k * 128;
        const float2 q = *reinterpret_cast<const float2*>(src + i * 6);
        const int yb = biny(q.y);
        if (yb >= r0 && yb <= r1)
            atomicAdd(&scnt[(yb - r0) * GBX + binx(q.x)], 1);
    }

    // ---- pred compaction: this CTA owns preds with (p&1)==half, row yr ----
    #pragma unroll
    for (int k = 0; k < 8; ++k) {
        const int p = 2 * (tid + k * 128) + half;
        const float y1 = pred[p * 6 + 1];
        if (biny(y1) == yr) {
            const int pos = atomicAdd(&npred_s, 1);
            if (pos < SPCAP) {
                const float2 q0 = *reinterpret_cast<const float2*>(pred + p * 6);
                const float2 q1 = *reinterpret_cast<const float2*>(pred + p * 6 + 2);
                spred[pos] = make_float4(q0.x, q0.y, q1.x, q1.y);
                sperm[pos] = p;
            } else {
                // overflow (never for uniform data): exact gmem full scan now
                const float2 q0 = *reinterpret_cast<const float2*>(pred + p * 6);
                const float2 q1 = *reinterpret_cast<const float2*>(pred + p * 6 + 2);
                const float4 a = make_float4(q0.x, q0.y, q1.x, q1.y);
                const float thr = (a.z - a.x) * (a.w - a.y) + EPS_F;
                float best = -1e30f;
                for (int m = 0; m < M_BOX; ++m) {
                    const float2 b0 = *reinterpret_cast<const float2*>(src + m * 6);
                    const float2 b1 = *reinterpret_cast<const float2*>(src + m * 6 + 2);
                    const float na = -((b1.x - b0.x) * (b1.y - b0.y));
                    IOU_CHECK(b0.x, b0.y, b1.x, b1.y, na);
                    if (best > thr) break;
                }
                const int f = (best > thr) ? 1 : 0;
                const int old = atomicAdd(&g_cnt[p], 0x10000 + f);
                if ((old >> 16) == T_RUNS - 1) {
                    out[p] = (float)((old & 0xffff) + f) * (1.0f / T_RUNS);
                    g_cnt[p] = 0;
                }
            }
        }
    }
    __syncthreads();

    // ---- exclusive scan over 256 bins (2 per thread, 4 warps) ----
    const int v0 = scnt[2 * tid], v1 = scnt[2 * tid + 1];
    const int tv = v0 + v1;
    int inc = tv;
    #pragma unroll
    for (int o = 1; o < 32; o <<= 1) {
        int nn = __shfl_up_sync(0xffffffffu, inc, o);
        if (lane >= o) inc += nn;
    }
    if (lane == 31) wsum[wid] = inc;
    __syncthreads();
    if (tid == 0) {
        int acc = 0;
        #pragma unroll
        for (int r = 0; r < 4; ++r) { int x = wsum[r]; wsum[r] = acc; acc += x; }
    }
    __syncthreads();
    const int start0 = inc - tv + wsum[wid];
    scnt[2 * tid]     = start0;       // pristine prefix for window queries
    scnt[2 * tid + 1] = start0 + v0;
    soff[2 * tid]     = start0;       // running offsets for scatter
    soff[2 * tid + 1] = start0 + v0;
    __syncthreads();

    const int total = scnt[nb];       // pad bins are zero-count
    const bool all_smem = (total <= CAP);

    // ---- pass 2: scatter boxes into the x-sorted smem slab ----
    if (all_smem) {
        #pragma unroll
        for (int k = 0; k < M_BOX / 128; ++k) {
            const int i = tid + k * 128;
            const float2 q0 = *reinterpret_cast<const float2*>(src + i * 6);
            const int yb = biny(q0.y);
            if (yb >= r0 && yb <= r1) {
                const int pos = atomicAdd(&soff[(yb - r0) * GBX + binx(q0.x)], 1);
                const float2 q1 = *reinterpret_cast<const float2*>(src + i * 6 + 2);
                sbox[pos]   = make_float4(q0.x, q0.y, q1.x, q1.y);
                snarea[pos] = -((q1.x - q0.x) * (q1.y - q0.y));
            }
        }
    }
    __syncthreads();

    // ---- scan phase (R13 champion loop) ----
    const int np = min(npred_s, SPCAP);
    for (int si = tid; si < np; si += 128) {
        const float4 a  = spred[si];
        const int    p  = sperm[si];
        const float thr = (a.z - a.x) * (a.w - a.y) + EPS_F;

        const int xb0 = binx(a.x - WH_MAX), xb1 = binx(a.z);
        const int yb0 = max(biny(a.y - WH_MAX), r0);
        const int yb1 = min(biny(a.w), r1);

        float best = -1e30f;
        if (all_smem) {
            for (int yb = yb0; yb <= yb1; ++yb) {
                const int rb = (yb - r0) * GBX;
                const int s  = scnt[rb + xb0];
                const int e  = scnt[rb + xb1 + 1];
                #pragma unroll 8
                for (int m = s; m < e; ++m) {
                    const float4 b = sbox[m];
                    IOU_CHECK(b.x, b.y, b.z, b.w, snarea[m]);
                }
                if (best > thr) break;
            }
        } else {                       // slab overflow: exact gmem full scan
            for (int m = 0; m < M_BOX; ++m) {
                const float2 b0 = *reinterpret_cast<const float2*>(src + m * 6);
                const float2 b1 = *reinterpret_cast<const float2*>(src + m * 6 + 2);
                const float na = -((b1.x - b0.x) * (b1.y - b0.y));
                IOU_CHECK(b0.x, b0.y, b1.x, b1.y, na);
                if (best > thr) break;
            }
        }

        // arrival protocol: 16th arrival writes the exact count / 16
        const int f = (best > thr) ? 1 : 0;
        const int old = atomicAdd(&g_cnt[p], 0x10000 + f);
        if ((old >> 16) == T_RUNS - 1) {
            out[p] = (float)((old & 0xffff) + f) * (1.0f / T_RUNS);
            g_cnt[p] = 0;              // reset scratch for the next replay
        }
    }
}

extern "C" void kernel_launch(void* const* d_in, const int* in_sizes, int n_in,
                              void* d_out, int out_size)
{
    const float* pred          = (const float*)d_in[0]; // [2048, 6]
    const float* dropout_preds = (const float*)d_in[1]; // [16, 2048, 6]
    // d_in[2] (dropout_cls_confs) unused by the reference computation.
    float* out = (float*)d_out;                          // [2048]

    fused_kernel<<<dim3(2, GBY, T_RUNS), 128>>>(pred, dropout_preds, out);
}

// round 15
// speedup vs baseline: 1.2003x; 1.2003x over previous
#include <cuda_runtime.h>
#include <cuda_bf16.h>

#define N_PRED 2048
#define T_RUNS 16
#define M_BOX  2048
#define EPS_F  1e-7f

#define GBY     16
#define GBX     32
#define NBINS   (GBY*GBX)       // 512
#define BIN_ORG (-28.0f)
#define INV_Y   (1.0f/42.0f)    // 16*42 = 672 covers [-28, 644)
#define INV_X   (1.0f/21.0f)    // 32*21 = 672
#define WH_MAX  55.0f           // box w,h in [5,55)
#define CAP     1280            // smem slab capacity (5 rows avg ~640)
#define SBW     (GBX + 1)       // 33 prefix entries per row
#define SPCAP   192             // smem pred-list capacity (half-row avg ~64)

// ---- device scratch (no allocations allowed; all reset by the protocols) ---
__device__ float4 g_sbox[T_RUNS][M_BOX];      // binned boxes (x1,y1,x2,y2)
__device__ int    g_bstart[T_RUNS][NBINS+1];  // bin prefix offsets per run
__device__ int    g_cnt[N_PRED];              // arrivals<<16 | found-sum
__device__ int    g_ready[T_RUNS];            // per-run sort-done flag
__device__ int    g_done[T_RUNS];             // per-run match-done counter

__device__ __forceinline__ int biny(float v) {
    int b = (int)floorf((v - BIN_ORG) * INV_Y);
    return min(max(b, 0), GBY - 1);
}
__device__ __forceinline__ int binx(float v) {
    int b = (int)floorf((v - BIN_ORG) * INV_X);
    return min(max(b, 0), GBX - 1);
}

#define IOU_CHECK(BX, BY, BZ, BW, NA)                            \
    {   float ix1 = fmaxf(a.x, (BX));                            \
        float iy1 = fmaxf(a.y, (BY));                            \
        float ix2 = fminf(a.z, (BZ));                            \
        float iy2 = fminf(a.w, (BW));                            \
        float dx  = fmaxf(ix2 - ix1, 0.0f);                      \
        float dy  = iy2 - iy1;   /* dy<0 => inter<=0 < thr */    \
        best = fmaxf(best, fmaf(3.0f, dx * dy, (NA))); }

// ---------------------------------------------------------------------------
// ONE kernel, 512 CTAs x 128 thr, all co-resident (smem 32KB -> 7 CTAs/SM).
// Linear CTA id < 16: additionally counting-sorts run id's boxes (shared by
// all 32 CTAs of that run). Per-run ready flags; local pred compaction
// overlaps the wait; then the R13 champion fill+scan; out via arrival counts.
// ---------------------------------------------------------------------------
__global__ __launch_bounds__(128)
void fused_kernel(const float* __restrict__ pred,
                  const float* __restrict__ dropout_preds,
                  float* __restrict__ out)
{
    __shared__ float4 sbox[CAP];
    __shared__ float  snarea[CAP];
    __shared__ int    scnt[NBINS];    // prep: counts -> running offsets
    __shared__ int    sbs[5 * SBW];   // match: prefix entries
    __shared__ float4 spred[SPCAP];
    __shared__ int    sperm[SPCAP];
    __shared__ int    wsum[4];
    __shared__ int    npred_s;

    const int tid  = threadIdx.x;
    const int lane = tid & 31, wid = tid >> 5;
    const int half = blockIdx.x;
    const int yr   = blockIdx.y;
    const int t    = blockIdx.z;
    const int cid  = half + 2 * (yr + GBY * t);   // linear CTA id

    if (tid == 0) npred_s = 0;

    // ================= prep duty: CTA cid<16 sorts run cid ================
    if (cid < T_RUNS) {
        const int pt = cid;
        const float* __restrict__ psrc = dropout_preds + (size_t)pt * M_BOX * 6;

        scnt[tid] = 0; scnt[tid + 128] = 0;
        scnt[tid + 256] = 0; scnt[tid + 384] = 0;
        __syncthreads();

        // count
        #pragma unroll
        for (int k = 0; k < M_BOX / 128; ++k) {
            const int i = tid + k * 128;
            const float2 q = *reinterpret_cast<const float2*>(psrc + i * 6);
            atomicAdd(&scnt[biny(q.y) * GBX + binx(q.x)], 1);
        }
        __syncthreads();

        // exclusive scan, 4 bins/thread
        const int b0 = scnt[4 * tid],     b1 = scnt[4 * tid + 1];
        const int b2 = scnt[4 * tid + 2], b3 = scnt[4 * tid + 3];
        const int tv = b0 + b1 + b2 + b3;
        int inc = tv;
        #pragma unroll
        for (int o = 1; o < 32; o <<= 1) {
            int nn = __shfl_up_sync(0xffffffffu, inc, o);
            if (lane >= o) inc += nn;
        }
        if (lane == 31) wsum[wid] = inc;
        __syncthreads();
        if (tid == 0) {
            int acc = 0;
            #pragma unroll
            for (int r = 0; r < 4; ++r) { int x = wsum[r]; wsum[r] = acc; acc += x; }
        }
        __syncthreads();
        int s0 = inc - tv + wsum[wid];
        const int s1 = s0 + b0, s2 = s1 + b1, s3 = s2 + b2;
        g_bstart[pt][4 * tid]     = s0;
        g_bstart[pt][4 * tid + 1] = s1;
        g_bstart[pt][4 * tid + 2] = s2;
        g_bstart[pt][4 * tid + 3] = s3;
        if (tid == 0) g_bstart[pt][NBINS] = M_BOX;
        scnt[4 * tid] = s0; scnt[4 * tid + 1] = s1;
        scnt[4 * tid + 2] = s2; scnt[4 * tid + 3] = s3;
        __syncthreads();

        // scatter
        #pragma unroll
        for (int k = 0; k < M_BOX / 128; ++k) {
            const int i = tid + k * 128;
            const float2 q0 = *reinterpret_cast<const float2*>(psrc + i * 6);
            const float2 q1 = *reinterpret_cast<const float2*>(psrc + i * 6 + 2);
            const int pos = atomicAdd(&scnt[biny(q0.y) * GBX + binx(q0.x)], 1);
            g_sbox[pt][pos] = make_float4(q0.x, q0.y, q1.x, q1.y);
        }
        __syncthreads();
        if (tid == 0) {
            __threadfence();
            atomicExch(&g_ready[pt], 1);
        }
    }

    // ============ local pred compaction (independent of prep) =============
    __syncthreads();
    #pragma unroll
    for (int k = 0; k < 8; ++k) {
        const int p = 2 * (tid + k * 128) + half;     // parity 'half' preds
        const float y1 = pred[p * 6 + 1];
        if (biny(y1) == yr) {
            const int pos = atomicAdd(&npred_s, 1);
            if (pos < SPCAP) {
                const float2 q0 = *reinterpret_cast<const float2*>(pred + p * 6);
                const float2 q1 = *reinterpret_cast<const float2*>(pred + p * 6 + 2);
                spred[pos] = make_float4(q0.x, q0.y, q1.x, q1.y);
                sperm[pos] = p;
            }
        }
    }

    // ================= wait for our run's sort =============================
    if (tid == 0) {
        while (atomicAdd(&g_ready[t], 0) == 0) __nanosleep(32);
    }
    __syncthreads();
    __threadfence();

    // ================= slab fill (R13 champion) ============================
    const int r0 = max(yr - 2, 0), r1 = min(yr + 2, GBY - 1);
    const int nr = r1 - r0 + 1;

    for (int i = tid; i < nr * SBW; i += 128) {
        const int r = i / SBW, b = i - r * SBW;
        sbs[i] = g_bstart[t][(r0 + r) * GBX + b];
    }
    __syncthreads();                   // sbs ready (also covers spred writes)

    const int base = sbs[0];
    const int n    = sbs[(nr - 1) * SBW + GBX] - base;
    const int ncap = min(n, CAP);
    for (int i = tid; i < ncap; i += 128) {
        float4 b  = g_sbox[t][base + i];
        sbox[i]   = b;
        snarea[i] = -((b.z - b.x) * (b.w - b.y));
    }
    __syncthreads();

    const bool all_smem = (n <= CAP);  // always true for uniform data
    const float* __restrict__ src = dropout_preds + (size_t)t * M_BOX * 6;

    // ================= scan (R13 champion loop) ============================
    const int np = min(npred_s, SPCAP);
    for (int si = tid; si < np; si += 128) {
        const float4 a  = spred[si];
        const int    p  = sperm[si];
        const float thr = (a.z - a.x) * (a.w - a.y) + EPS_F;

        const int xb0 = binx(a.x - WH_MAX), xb1 = binx(a.z);
        const int yb0 = max(biny(a.y - WH_MAX), r0);
        const int yb1 = min(biny(a.w), r1);

        float best = -1e30f;
        if (all_smem) {
            for (int yb = yb0; yb <= yb1; ++yb) {
                const int rb = (yb - r0) * SBW;
                const int s  = sbs[rb + xb0] - base;
                const int e  = sbs[rb + xb1 + 1] - base;
                #pragma unroll 8
                for (int m = s; m < e; ++m) {
                    const float4 b = sbox[m];
                    IOU_CHECK(b.x, b.y, b.z, b.w, snarea[m]);
                }
                if (best > thr) break;
            }
        } else {                       // overflow: exact full gmem scan
            for (int m = 0; m < M_BOX; ++m) {
                const float2 b0 = *reinterpret_cast<const float2*>(src + m * 6);
                const float2 b1 = *reinterpret_cast<const float2*>(src + m * 6 + 2);
                const float na = -((b1.x - b0.x) * (b1.y - b0.y));
                IOU_CHECK(b0.x, b0.y, b1.x, b1.y, na);
                if (best > thr) break;
            }
        }

        // arrival protocol: 16th arrival writes exact count/16, resets slot
        const int f = (best > thr) ? 1 : 0;
        const int old = atomicAdd(&g_cnt[p], 0x10000 + f);
        if ((old >> 16) == T_RUNS - 1) {
            out[p] = (float)((old & 0xffff) + f) * (1.0f / T_RUNS);
            g_cnt[p] = 0;
        }
    }

    // overflow preds (pos >= SPCAP): exact full scan (never for uniform data)
    if (npred_s > SPCAP) {
        for (int k = 0; k < 8; ++k) {
            const int p = 2 * (tid + k * 128) + half;
            const float y1 = pred[p * 6 + 1];
            if (biny(y1) != yr) continue;
            bool staged = false;
            for (int si = 0; si < np; ++si) if (sperm[si] == p) { staged = true; break; }
            if (staged) continue;
            const float2 q0 = *reinterpret_cast<const float2*>(pred + p * 6);
            const float2 q1 = *reinterpret_cast<const float2*>(pred + p * 6 + 2);
            const float4 a = make_float4(q0.x, q0.y, q1.x, q1.y);
            const float thr = (a.z - a.x) * (a.w - a.y) + EPS_F;
            float best = -1e30f;
            for (int m = 0; m < M_BOX; ++m) {
                const float2 b0 = *reinterpret_cast<const float2*>(src + m * 6);
                const float2 b1 = *reinterpret_cast<const float2*>(src + m * 6 + 2);
                const float na = -((b1.x - b0.x) * (b1.y - b0.y));
                IOU_CHECK(b0.x, b0.y, b1.x, b1.y, na);
                if (best > thr) break;
            }
            const int f = (best > thr) ? 1 : 0;
            const int old = atomicAdd(&g_cnt[p], 0x10000 + f);
            if ((old >> 16) == T_RUNS - 1) {
                out[p] = (float)((old & 0xffff) + f) * (1.0f / T_RUNS);
                g_cnt[p] = 0;
            }
        }
    }

    // ================= per-run teardown (replay-safe) ======================
    __syncthreads();
    if (tid == 0) {
        __threadfence();
        const int d = atomicAdd(&g_done[t], 1);
        if (d == 2 * GBY - 1) {        // last of the 32 CTAs of run t
            g_done[t]  = 0;
            g_ready[t] = 0;
        }
    }
}

extern "C" void kernel_launch(void* const* d_in, const int* in_sizes, int n_in,
                              void* d_out, int out_size)
{
    const float* pred          = (const float*)d_in[0]; // [2048, 6]
    const float* dropout_preds = (const float*)d_in[1]; // [16, 2048, 6]
    // d_in[2] (dropout_cls_confs) unused by the reference computation.
    float* out = (float*)d_out;                          // [2048]

    fused_kernel<<<dim3(2, GBY, T_RUNS), 128>>>(pred, dropout_preds, out);
}